// round 3
// baseline (speedup 1.0000x reference)
#include <cuda_runtime.h>
#include <cstdint>

// ============================================================================
// Problem constants  (784 = 49 * 16 exactly -> no K padding needed)
// ============================================================================
#define KDIM      784
#define KCH       16          // K per pipeline chunk
#define NCHUNK    49          // KDIM / KCH
#define MT        128         // M tile per CTA
#define NT        128         // N tile per CTA
#define NSTAGES   4
#define THREADS   512         // 16 warps: 4 in M x 4 in N, warp tile M32xN32

// Shared tile pitch: 20 floats/row -> 80 B (16B-aligned for cp.async) and the
// fragment pattern (rows stride PITCH, tk in 0..3/+4) is bank-conflict-free
// (tg*20 mod 32 = {0,20,8,28,16,4,24,12}).
#define PITCH     20
#define STAGE_F   ((MT + NT) * PITCH)      // floats per stage = 5120 (A then B)

// smem float offsets
#define OF_PIPE   0                        // 4*5120 = 20480 floats (81920 B)
#define OF_W2     20480                    // 1280
#define OF_B1     21760                    // 128
#define OF_B2     21888                    // 16 (10 used)
#define SMEM_FLOATS 21904
#define SMEM_BYTES  (SMEM_FLOATS * 4)      // 87616 -> 2 CTAs/SM
// epilogue overlays (pipeline region is dead by then):
#define OF_PART   0                        // 4 * 128 * 10 = 5120
#define OF_OUTS   5120                     // 1280

// W_eff transposed: g_Wt[n*784 + k] = W_eff[k][n], tf32-RNA-rounded
__device__ __align__(16) float g_Wt[NT * KDIM];

// ============================================================================
// helpers (baseline PTX only — no 'a'-suffix features survive compute_103)
// ============================================================================
__device__ __forceinline__ uint32_t smem_u32(const void* p) {
    uint32_t a;
    asm("{ .reg .u64 t; cvta.to.shared.u64 t, %1; cvt.u32.u64 %0, t; }" : "=r"(a) : "l"(p));
    return a;
}
__device__ __forceinline__ uint32_t f2tf32(float f) {
    uint32_t r;
    asm("cvt.rna.tf32.f32 %0, %1;" : "=r"(r) : "f"(f));
    return r;
}
__device__ __forceinline__ void cp_async16(uint32_t dst_smem, const void* src) {
    asm volatile("cp.async.cg.shared.global [%0], [%1], 16;" :: "r"(dst_smem), "l"(src) : "memory");
}
__device__ __forceinline__ void cp_commit() {
    asm volatile("cp.async.commit_group;" ::: "memory");
}
__device__ __forceinline__ void cp_wait2() {
    asm volatile("cp.async.wait_group 2;" ::: "memory");
}
__device__ __forceinline__ void cp_wait0() {
    asm volatile("cp.async.wait_group 0;" ::: "memory");
}
__device__ __forceinline__ void mma_tf32(float* c, const uint32_t* a, const uint32_t* b) {
    asm volatile("mma.sync.aligned.m16n8k8.row.col.f32.tf32.tf32.f32 "
                 "{%0,%1,%2,%3}, {%4,%5,%6,%7}, {%8,%9}, {%0,%1,%2,%3};"
                 : "+f"(c[0]), "+f"(c[1]), "+f"(c[2]), "+f"(c[3])
                 : "r"(a[0]), "r"(a[1]), "r"(a[2]), "r"(a[3]), "r"(b[0]), "r"(b[1]));
}

// ============================================================================
// Prep kernel: W_eff^T = (conv ⊗ w1), tf32-RNA rounded (exact under HW trunc)
// ============================================================================
__global__ void prep_kernel(const float* __restrict__ conv_w, const float* __restrict__ w1) {
    int idx = blockIdx.x * blockDim.x + threadIdx.x;
    if (idx >= NT * KDIM) return;
    int n = idx / KDIM;
    int k = idx - n * KDIM;
    int i = k / 28, j = k - (k / 28) * 28;
    float v = 0.f;
    #pragma unroll
    for (int dy = 0; dy < 3; ++dy) {
        int r = i - dy;
        if (r < 0 || r >= 26) continue;
        #pragma unroll
        for (int dx = 0; dx < 3; ++dx) {
            int c = j - dx;
            if (c < 0 || c >= 26) continue;
            v += conv_w[dy * 3 + dx] * w1[(r * 26 + c) * 128 + n];
        }
    }
    g_Wt[idx] = __uint_as_float(f2tf32(v));
}

// ============================================================================
// Main fused kernel: out = relu(x @ W_eff + b1) @ w2 + b2
// ============================================================================
__global__ void __launch_bounds__(THREADS, 2)
fused_mlp_kernel(const float* __restrict__ x, const float* __restrict__ b1,
                 const float* __restrict__ w2, const float* __restrict__ b2,
                 float* __restrict__ out, int Brows) {
    extern __shared__ float sm[];
    const int tid  = threadIdx.x;
    const int wid  = tid >> 5;
    const int lane = tid & 31;
    const int tg   = lane >> 2;          // 0..7
    const int tk   = lane & 3;           // 0..3
    const int mw   = (wid >> 2) * 32;    // 4 warps in M
    const int nw   = (wid & 3) * 32;     // 4 warps in N
    const int m0   = blockIdx.x * MT;

    // constants into smem
    for (int i = tid; i < 1280; i += THREADS) sm[OF_W2 + i] = w2[i];
    if (tid < 128) sm[OF_B1 + tid] = b1[tid];
    if (tid < 10)  sm[OF_B2 + tid] = b2[tid];

    const uint32_t pipe_sm = smem_u32(sm + OF_PIPE);

    // per-thread producer addressing: one A cp.async + one B cp.async per chunk
    const int prow = tid >> 2;           // 0..127
    const int pq   = tid & 3;            // quad (16 B) within the 64 B chunk row
    int msrc = m0 + prow; if (msrc >= Brows) msrc = Brows - 1;
    const float* xsrc = x + (size_t)msrc * KDIM + pq * 4;
    const float* wsrc = g_Wt + (size_t)prow * KDIM + pq * 4;
    const uint32_t adst = (uint32_t)(prow * PITCH + pq * 4) * 4;
    const uint32_t bdst = adst + (uint32_t)(MT * PITCH) * 4;

    auto issue = [&](int c, int stage) {
        const uint32_t s = pipe_sm + (uint32_t)stage * (STAGE_F * 4);
        cp_async16(s + adst, xsrc + c * KCH);
        cp_async16(s + bdst, wsrc + c * KCH);
    };

    float acc[2][4][4];
    #pragma unroll
    for (int mi = 0; mi < 2; ++mi)
        #pragma unroll
        for (int ni = 0; ni < 4; ++ni)
            #pragma unroll
            for (int e = 0; e < 4; ++e) acc[mi][ni][e] = 0.f;

    // prologue: fill 3 stages
    #pragma unroll
    for (int c = 0; c < NSTAGES - 1; ++c) { issue(c, c); cp_commit(); }

    // ---- mainloop ----
    for (int c = 0; c < NCHUNK; ++c) {
        cp_wait2();
        __syncthreads();

        const int cn = c + NSTAGES - 1;
        if (cn < NCHUNK) issue(cn, cn & (NSTAGES - 1));
        cp_commit();

        const float* As = sm + OF_PIPE + (c & (NSTAGES - 1)) * STAGE_F;
        const float* Bs = As + MT * PITCH;

        #pragma unroll
        for (int ks = 0; ks < KCH; ks += 8) {
            uint32_t a[2][4];
            #pragma unroll
            for (int mi = 0; mi < 2; ++mi) {
                const int base = (mw + mi * 16 + tg) * PITCH + ks + tk;
                a[mi][0] = f2tf32(As[base]);
                a[mi][1] = f2tf32(As[base + 8 * PITCH]);
                a[mi][2] = f2tf32(As[base + 4]);
                a[mi][3] = f2tf32(As[base + 8 * PITCH + 4]);
            }
            uint32_t b[4][2];
            #pragma unroll
            for (int ni = 0; ni < 4; ++ni) {
                const int nb = (nw + ni * 8 + tg) * PITCH + ks + tk;
                b[ni][0] = __float_as_uint(Bs[nb]);       // pre-rounded: HW trunc exact
                b[ni][1] = __float_as_uint(Bs[nb + 4]);
            }
            #pragma unroll
            for (int mi = 0; mi < 2; ++mi)
                #pragma unroll
                for (int ni = 0; ni < 4; ++ni)
                    mma_tf32(acc[mi][ni], a[mi], b[ni]);
        }
    }

    // ---- epilogue: GEMM2 directly from registers (no h staging) ----
    cp_wait0();
    __syncthreads();    // pipeline region dead -> safe to overlay part/outs

    float* part = sm + OF_PART;     // [4 n-warps][128 rows][10]
    #pragma unroll
    for (int s = 0; s < 4; ++s) {   // row slot: r = mw + tg + 8*s
        const int mi = s >> 1;
        const int e0 = (s & 1) ? 2 : 0;
        float o[10];
        #pragma unroll
        for (int j = 0; j < 10; ++j) o[j] = 0.f;
        #pragma unroll
        for (int ni = 0; ni < 4; ++ni) {
            const int n = nw + ni * 8 + 2 * tk;
            const float t0 = fmaxf(acc[mi][ni][e0]     + sm[OF_B1 + n],     0.f);
            const float t1 = fmaxf(acc[mi][ni][e0 + 1] + sm[OF_B1 + n + 1], 0.f);
            const float* w0 = sm + OF_W2 + n * 10;
            #pragma unroll
            for (int j = 0; j < 10; ++j) o[j] = fmaf(t0, w0[j], fmaf(t1, w0[10 + j], o[j]));
        }
        #pragma unroll
        for (int j = 0; j < 10; ++j) {
            o[j] += __shfl_xor_sync(0xFFFFFFFF, o[j], 1);
            o[j] += __shfl_xor_sync(0xFFFFFFFF, o[j], 2);
        }
        if (tk == 0) {
            const int r = mw + tg + 8 * s;
            #pragma unroll
            for (int j = 0; j < 10; ++j) part[(wid & 3) * 1280 + r * 10 + j] = o[j];
        }
    }
    __syncthreads();

    // final 4-way reduce + b2
    if (tid < 128) {
        #pragma unroll
        for (int j = 0; j < 10; ++j)
            sm[OF_OUTS + tid * 10 + j] = part[tid * 10 + j] + part[1280 + tid * 10 + j]
                                       + part[2560 + tid * 10 + j] + part[3840 + tid * 10 + j]
                                       + sm[OF_B2 + j];
    }
    __syncthreads();

    // coalesced store
    const int nvalid = (Brows - m0 < MT) ? (Brows - m0) : MT;
    if (nvalid == MT) {
        float4* dst = (float4*)(out + (size_t)m0 * 10);
        const float4* src = (const float4*)(sm + OF_OUTS);
        if (tid < MT * 10 / 4) dst[tid] = src[tid];
    } else {
        for (int i = tid; i < nvalid * 10; i += THREADS) out[(size_t)m0 * 10 + i] = sm[OF_OUTS + i];
    }
}

// ============================================================================
// Host launch
// ============================================================================
extern "C" void kernel_launch(void* const* d_in, const int* in_sizes, int n_in,
                              void* d_out, int out_size) {
    const float* x      = (const float*)d_in[0];
    const float* conv_w = (const float*)d_in[1];
    const float* w1     = (const float*)d_in[2];
    const float* b1     = (const float*)d_in[3];
    const float* w2     = (const float*)d_in[4];
    const float* b2     = (const float*)d_in[5];
    float* out          = (float*)d_out;
    const int Brows     = in_sizes[0] / KDIM;

    static int configured = 0;
    if (!configured) {
        cudaFuncSetAttribute(fused_mlp_kernel, cudaFuncAttributeMaxDynamicSharedMemorySize, SMEM_BYTES);
        configured = 1;
    }

    prep_kernel<<<(NT * KDIM + 255) / 256, 256>>>(conv_w, w1);

    const int grid = (Brows + MT - 1) / MT;
    fused_mlp_kernel<<<grid, THREADS, SMEM_BYTES>>>(x, b1, w2, b2, out, Brows);
}

// round 4
// speedup vs baseline: 1.9192x; 1.9192x over previous
#include <cuda_runtime.h>
#include <cuda_fp16.h>
#include <cstdint>

// ============================================================================
// Problem constants — fp16 MMA path, K padded 784 -> 800 (25 chunks of 32)
// ============================================================================
#define KDIM      784
#define KPAD      800
#define KCH       32          // K per pipeline chunk
#define NCHUNK    25          // KPAD / KCH
#define MT        128         // M tile per CTA
#define NT        128         // N tile per CTA
#define NSTAGES   3
#define THREADS   256         // 8 warps: 4 in M x 2 in N, warp tile M32xN64

// A tile: fp32, pitch 40 floats (160 B). LDS.64 pattern (tg*40+2tk)*4B is
// conflict-free per 16-lane phase. B tile: fp16, pitch 40 halves (80 B).
// b32 LDS pattern n*20+tk covers all 32 banks exactly once.
#define APITCH    40          // floats
#define BPITCH    40          // halves
#define A_STAGE_F (MT * APITCH)            // 5120 floats = 20480 B
#define B_STAGE_H (NT * BPITCH)            // 5120 halves = 10240 B
#define STAGE_F   (A_STAGE_F + B_STAGE_H / 2)   // 7680 floats = 30720 B
#define PH        130                      // h staging pitch (floats)

// smem float offsets
#define OF_PIPE   0                        // 3*7680 = 23040 floats (92160 B)
#define OF_W2     23040                    // 1280
#define OF_B1     24320                    // 128
#define OF_B2     24448                    // 16 (10 used)
#define SMEM_FLOATS 24464
#define SMEM_BYTES  (SMEM_FLOATS * 4)      // 97856 -> 2 CTAs/SM
// epilogue overlays (pipeline region dead by then): h[128][130] = 16640 floats
#define OF_PART   16640                    // 256*10 = 2560
#define OF_OUTS   19200                    // 1280

// W_eff transposed, fp16-RN: g_Wt16[n*KPAD + k] = fp16(W_eff[k][n]), 0 for k>=784
__device__ __align__(16) __half g_Wt16[NT * KPAD];

// ============================================================================
// helpers (baseline PTX only — no 'a'-suffix features survive compute_103)
// ============================================================================
__device__ __forceinline__ uint32_t smem_u32(const void* p) {
    uint32_t a;
    asm("{ .reg .u64 t; cvta.to.shared.u64 t, %1; cvt.u32.u64 %0, t; }" : "=r"(a) : "l"(p));
    return a;
}
__device__ __forceinline__ uint32_t pack_f16x2(float lo, float hi) {
    uint32_t r;
    asm("cvt.rn.f16x2.f32 %0, %2, %1;" : "=r"(r) : "f"(lo), "f"(hi));  // hi goes to upper half
    return r;
}
__device__ __forceinline__ void cp_async16(uint32_t dst_smem, const void* src) {
    asm volatile("cp.async.cg.shared.global [%0], [%1], 16;" :: "r"(dst_smem), "l"(src) : "memory");
}
__device__ __forceinline__ void cp_async16_pred(uint32_t dst_smem, const void* src, int src_bytes) {
    asm volatile("cp.async.cg.shared.global [%0], [%1], 16, %2;"
                 :: "r"(dst_smem), "l"(src), "r"(src_bytes) : "memory");
}
__device__ __forceinline__ void cp_commit() { asm volatile("cp.async.commit_group;" ::: "memory"); }
__device__ __forceinline__ void cp_wait1()  { asm volatile("cp.async.wait_group 1;" ::: "memory"); }
__device__ __forceinline__ void cp_wait0()  { asm volatile("cp.async.wait_group 0;" ::: "memory"); }

__device__ __forceinline__ void mma_f16(float* c, const uint32_t* a, const uint32_t* b) {
    asm volatile("mma.sync.aligned.m16n8k16.row.col.f32.f16.f16.f32 "
                 "{%0,%1,%2,%3}, {%4,%5,%6,%7}, {%8,%9}, {%0,%1,%2,%3};"
                 : "+f"(c[0]), "+f"(c[1]), "+f"(c[2]), "+f"(c[3])
                 : "r"(a[0]), "r"(a[1]), "r"(a[2]), "r"(a[3]), "r"(b[0]), "r"(b[1]));
}

// ============================================================================
// Prep kernel: W_eff^T = (conv ⊗ w1), fp16-RN (same 10-bit mantissa as tf32)
// ============================================================================
__global__ void prep_kernel(const float* __restrict__ conv_w, const float* __restrict__ w1) {
    int idx = blockIdx.x * blockDim.x + threadIdx.x;
    if (idx >= NT * KPAD) return;
    int n = idx / KPAD;
    int k = idx - n * KPAD;
    float v = 0.f;
    if (k < KDIM) {
        int i = k / 28, j = k - (k / 28) * 28;
        #pragma unroll
        for (int dy = 0; dy < 3; ++dy) {
            int r = i - dy;
            if (r < 0 || r >= 26) continue;
            #pragma unroll
            for (int dx = 0; dx < 3; ++dx) {
                int c = j - dx;
                if (c < 0 || c >= 26) continue;
                v += conv_w[dy * 3 + dx] * w1[(r * 26 + c) * 128 + n];
            }
        }
    }
    g_Wt16[idx] = __float2half_rn(v);
}

// ============================================================================
// Main fused kernel: out = relu(x @ W_eff + b1) @ w2 + b2
// ============================================================================
__global__ void __launch_bounds__(THREADS, 2)
fused_mlp_kernel(const float* __restrict__ x, const float* __restrict__ b1,
                 const float* __restrict__ w2, const float* __restrict__ b2,
                 float* __restrict__ out, int Brows) {
    extern __shared__ float sm[];
    const int tid  = threadIdx.x;
    const int wid  = tid >> 5;
    const int lane = tid & 31;
    const int tg   = lane >> 2;          // 0..7
    const int tk   = lane & 3;           // 0..3
    const int mw   = (wid >> 1) * 32;    // 4 warps in M
    const int nw   = (wid & 1) * 64;     // 2 warps in N
    const int m0   = blockIdx.x * MT;

    // constants into smem
    for (int i = tid; i < 1280; i += THREADS) sm[OF_W2 + i] = w2[i];
    if (tid < 128) sm[OF_B1 + tid] = b1[tid];
    if (tid < 10)  sm[OF_B2 + tid] = b2[tid];

    const uint32_t pipe_sm = smem_u32(sm + OF_PIPE);

    // ---- producer: A = 4 x 16B pieces/thread (zero-fill past K=784), B = 2 pieces ----
    auto issue = [&](int c, int stage) {
        const uint32_t sbase = pipe_sm + (uint32_t)stage * (STAGE_F * 4);
        #pragma unroll
        for (int r = 0; r < 4; ++r) {
            const int j   = tid + r * THREADS;       // 0..1023
            const int row = j >> 3, q = j & 7;       // row, 16B piece (4 floats)
            int msrc = m0 + row; if (msrc >= Brows) msrc = Brows - 1;
            const int k0 = c * KCH + q * 4;
            cp_async16_pred(sbase + (uint32_t)(row * APITCH + q * 4) * 4,
                            x + (size_t)msrc * KDIM + k0,
                            (k0 < KDIM) ? 16 : 0);
        }
        const uint32_t bbase = sbase + A_STAGE_F * 4;
        #pragma unroll
        for (int r = 0; r < 2; ++r) {
            const int j   = tid + r * THREADS;       // 0..511
            const int row = j >> 2, q = j & 3;       // row, 16B piece (8 halves)
            cp_async16(bbase + (uint32_t)(row * BPITCH + q * 8) * 2,
                       g_Wt16 + (size_t)row * KPAD + c * KCH + q * 8);
        }
    };

    float acc[2][8][4];
    #pragma unroll
    for (int mi = 0; mi < 2; ++mi)
        #pragma unroll
        for (int ni = 0; ni < 8; ++ni)
            #pragma unroll
            for (int e = 0; e < 4; ++e) acc[mi][ni][e] = 0.f;

    // prologue: fill 2 stages
    issue(0, 0); cp_commit();
    issue(1, 1); cp_commit();

    // ---- mainloop ----
    int stage = 0;
    for (int c = 0; c < NCHUNK; ++c) {
        cp_wait1();
        __syncthreads();

        const int cn = c + NSTAGES - 1;
        int nstage = stage + 2; if (nstage >= NSTAGES) nstage -= NSTAGES;
        if (cn < NCHUNK) issue(cn, nstage);
        cp_commit();

        const float* As = sm + OF_PIPE + stage * STAGE_F;
        const uint32_t* Bs32 = (const uint32_t*)(As + A_STAGE_F);

        #pragma unroll
        for (int ks = 0; ks < KCH; ks += 16) {
            // A fragments: m16n8k16 -> 4 regs, each = 2 consecutive fp32 -> f16x2
            uint32_t a[2][4];
            #pragma unroll
            for (int mi = 0; mi < 2; ++mi) {
                const float2* r0 = (const float2*)(As + (mw + mi * 16 + tg) * APITCH + ks);
                const float2* r1 = (const float2*)(As + (mw + mi * 16 + tg + 8) * APITCH + ks);
                float2 v0 = r0[tk], v1 = r1[tk], v2 = r0[tk + 4], v3 = r1[tk + 4];
                a[mi][0] = pack_f16x2(v0.x, v0.y);
                a[mi][1] = pack_f16x2(v1.x, v1.y);
                a[mi][2] = pack_f16x2(v2.x, v2.y);
                a[mi][3] = pack_f16x2(v3.x, v3.y);
            }
            // B fragments: fp16 already in smem, b32 picks (k=2tk,2tk+1 | +8)
            uint32_t b[8][2];
            #pragma unroll
            for (int ni = 0; ni < 8; ++ni) {
                const uint32_t* bn = Bs32 + (nw + ni * 8 + tg) * (BPITCH / 2) + (ks / 2);
                b[ni][0] = bn[tk];
                b[ni][1] = bn[tk + 4];
            }
            #pragma unroll
            for (int mi = 0; mi < 2; ++mi)
                #pragma unroll
                for (int ni = 0; ni < 8; ++ni)
                    mma_f16(acc[mi][ni], a[mi], b[ni]);
        }
        ++stage; if (stage >= NSTAGES) stage = 0;
    }

    // ---- epilogue: h = relu(acc + b1) into smem overlay ----
    cp_wait0();
    __syncthreads();   // pipeline reads done before overlay
    {
        float* h = sm + OF_PIPE;   // [128][PH]
        #pragma unroll
        for (int mi = 0; mi < 2; ++mi) {
            #pragma unroll
            for (int ni = 0; ni < 8; ++ni) {
                const int r = mw + mi * 16 + tg;
                const int n = nw + ni * 8 + 2 * tk;
                const float bn0 = sm[OF_B1 + n], bn1 = sm[OF_B1 + n + 1];
                h[r * PH + n]           = fmaxf(acc[mi][ni][0] + bn0, 0.f);
                h[r * PH + n + 1]       = fmaxf(acc[mi][ni][1] + bn1, 0.f);
                h[(r + 8) * PH + n]     = fmaxf(acc[mi][ni][2] + bn0, 0.f);
                h[(r + 8) * PH + n + 1] = fmaxf(acc[mi][ni][3] + bn1, 0.f);
            }
        }
    }
    __syncthreads();

    // ---- GEMM2: split-K over 2 threads/row ----
    {
        const float* h = sm + OF_PIPE;
        const int row  = tid & 127;
        const int half = tid >> 7;
        float o[10];
        #pragma unroll
        for (int n = 0; n < 10; ++n) o[n] = 0.f;
        #pragma unroll 8
        for (int k = half * 64; k < half * 64 + 64; ++k) {
            const float t = h[row * PH + k];
            const float* wr = sm + OF_W2 + k * 10;
            #pragma unroll
            for (int n = 0; n < 10; ++n) o[n] = fmaf(t, wr[n], o[n]);
        }
        #pragma unroll
        for (int n = 0; n < 10; ++n) sm[OF_PART + tid * 10 + n] = o[n];
    }
    __syncthreads();
    if (tid < 128) {
        #pragma unroll
        for (int n = 0; n < 10; ++n)
            sm[OF_OUTS + tid * 10 + n] = sm[OF_PART + tid * 10 + n]
                                       + sm[OF_PART + (tid + 128) * 10 + n]
                                       + sm[OF_B2 + n];
    }
    __syncthreads();

    // ---- coalesced store ----
    const int nvalid = (Brows - m0 < MT) ? (Brows - m0) : MT;
    if (nvalid == MT) {
        float4* dst = (float4*)(out + (size_t)m0 * 10);
        const float4* src = (const float4*)(sm + OF_OUTS);
        for (int i = tid; i < MT * 10 / 4; i += THREADS) dst[i] = src[i];
    } else {
        for (int i = tid; i < nvalid * 10; i += THREADS) out[(size_t)m0 * 10 + i] = sm[OF_OUTS + i];
    }
}

// ============================================================================
// Host launch
// ============================================================================
extern "C" void kernel_launch(void* const* d_in, const int* in_sizes, int n_in,
                              void* d_out, int out_size) {
    const float* x      = (const float*)d_in[0];
    const float* conv_w = (const float*)d_in[1];
    const float* w1     = (const float*)d_in[2];
    const float* b1     = (const float*)d_in[3];
    const float* w2     = (const float*)d_in[4];
    const float* b2     = (const float*)d_in[5];
    float* out          = (float*)d_out;
    const int Brows     = in_sizes[0] / KDIM;

    static int configured = 0;
    if (!configured) {
        cudaFuncSetAttribute(fused_mlp_kernel, cudaFuncAttributeMaxDynamicSharedMemorySize, SMEM_BYTES);
        configured = 1;
    }

    prep_kernel<<<(NT * KPAD + 255) / 256, 256>>>(conv_w, w1);

    const int grid = (Brows + MT - 1) / MT;
    fused_mlp_kernel<<<grid, THREADS, SMEM_BYTES>>>(x, b1, w2, b2, out, Brows);
}